// round 10
// baseline (speedup 1.0000x reference)
#include <cuda_runtime.h>
#include <cstdint>

typedef unsigned long long ull;

#define H     51
#define GP    208         // gate cols (204 real, interleaved col = 4u+g)
#define GROW  212         // split-buffer row stride (floats)
#define SZ_G  (8*GROW)    // 1696
#define HR    60          // plain h row stride (56 used, bank-clean stores)
#define TSEQ  512
#define FUT   64
#define TTOT  (TSEQ + FUT)
#define NT    256         // 8 warps = 2 j-slices x 4 k-splits
#define INROW 516
#define WROW  416         // pair-layout weight row: 208 cols x 2 floats

// ---- smem layout (float offsets) ----
#define OFF_W1P 0                         // 28 kp-rows x 416
#define SZ_W1P  (28*WROW)                 // 11648
#define OFF_W2P (OFF_W1P + SZ_W1P)        // 52 kp-rows x 416
#define SZ_W2P  (52*WROW)                 // 21632
#define OFF_WX  (OFF_W2P + SZ_W2P)        // 33280
#define OFF_B1  (OFF_WX + GP)
#define OFF_B2  (OFF_B1 + GP)
#define OFF_WL  (OFF_B2 + GP)             // 64
#define OFF_IN  (OFF_WL + 64)             // 8*516
#define OFF_H1  (OFF_IN + 8*INROW)        // 8*60
#define OFF_H2  (OFF_H1 + 8*HR)
#define OFF_G1  (OFF_H2 + 8*HR)           // 4*1696
#define OFF_G2  (OFF_G1 + 4*SZ_G)
#define OFF_OUT (OFF_G2 + 4*SZ_G)
#define OFF_BL  (OFF_OUT + 8)
#define SMEM_FLOATS (OFF_BL + 8)          // ~52644 -> ~210.6 KB
#define SMEM_BYTES  (SMEM_FLOATS * 4)

__device__ __forceinline__ ull ffma2(ull a, ull b, ull c) {
    ull d;
    asm("fma.rn.f32x2 %0, %1, %2, %3;" : "=l"(d) : "l"(a), "l"(b), "l"(c));
    return d;
}

__device__ __forceinline__ float foldadd(ull a) {
    float lo, hi;
    asm("mov.b64 {%0,%1}, %2;" : "=f"(lo), "=f"(hi) : "l"(a));
    return lo + hi;
}

__device__ __forceinline__ float fex2(float x) {
    float r;
    asm("ex2.approx.f32 %0, %1;" : "=f"(r) : "f"(x));
    return r;
}

__device__ __forceinline__ float frcp(float x) {
    float r;
    asm("rcp.approx.f32 %0, %1;" : "=f"(r) : "f"(x));
    return r;
}

// LSTM cell update, 5 EX2 + 2 RCP (common-denominator form, R8-validated).
__device__ __forceinline__ float cellup(float gi, float gf, float gg, float go,
                                        float& c)
{
    const float L2E = 1.4426950408889634f;
    float ei = fex2(-L2E * gi);
    float ef = fex2(-L2E * gf);
    float eg = fex2(-2.0f * L2E * fabsf(gg));
    float pi = 1.0f + ei, pf = 1.0f + ef, pg = 1.0f + eg;
    float tg = copysignf(1.0f - eg, gg);
    float num = c * pi * pg + tg * pf;
    c = num * frcp(pf * pi * pg);
    float eo = fex2(-L2E * go);
    float ec = fex2(-2.0f * L2E * fabsf(c));
    return copysignf(1.0f - ec, c) * frcp((1.0f + eo) * (1.0f + ec));
}

// K-parity matvec over NQ quads (4 k each). acc f32x2 = (even-k, odd-k)
// partials of ONE column; h loaded plain (no duplication, no movs).
// Per quad: 4 weight LDS.128 + 8 broadcast h LDS.128 -> 64 FFMA2.
template<int NQ>
__device__ __forceinline__ void mvp(const float* __restrict__ wp,
                                    const float* __restrict__ hb,
                                    float* __restrict__ gout, int j0)
{
    ull acc[8][4];
    #pragma unroll
    for (int b = 0; b < 8; ++b) {
        #pragma unroll
        for (int c = 0; c < 4; ++c) acc[b][c] = 0ull;
    }
    #pragma unroll
    for (int q = 0; q < NQ; ++q) {
        const float* ra = wp + (2*q  )*WROW + 2*j0;   // kp = 2q   (h .x)
        const float* rb = wp + (2*q+1)*WROW + 2*j0;   // kp = 2q+1 (h .y)
        ulonglong2 wa0 = *reinterpret_cast<const ulonglong2*>(ra);
        ulonglong2 wa1 = *reinterpret_cast<const ulonglong2*>(ra + 4);
        ulonglong2 wb0 = *reinterpret_cast<const ulonglong2*>(rb);
        ulonglong2 wb1 = *reinterpret_cast<const ulonglong2*>(rb + 4);
        #pragma unroll
        for (int b = 0; b < 8; ++b) {
            ulonglong2 hv = *reinterpret_cast<const ulonglong2*>(hb + b*HR + 4*q);
            acc[b][0] = ffma2(wa0.x, hv.x, acc[b][0]);
            acc[b][1] = ffma2(wa0.y, hv.x, acc[b][1]);
            acc[b][2] = ffma2(wa1.x, hv.x, acc[b][2]);
            acc[b][3] = ffma2(wa1.y, hv.x, acc[b][3]);
            acc[b][0] = ffma2(wb0.x, hv.y, acc[b][0]);
            acc[b][1] = ffma2(wb0.y, hv.y, acc[b][1]);
            acc[b][2] = ffma2(wb1.x, hv.y, acc[b][2]);
            acc[b][3] = ffma2(wb1.y, hv.y, acc[b][3]);
        }
    }
    #pragma unroll
    for (int b = 0; b < 8; ++b) {
        float4 r;
        r.x = foldadd(acc[b][0]);
        r.y = foldadd(acc[b][1]);
        r.z = foldadd(acc[b][2]);
        r.w = foldadd(acc[b][3]);
        *reinterpret_cast<float4*>(gout + b*GROW + j0) = r;
    }
}

// gate tasks: 408 (b,hu) over 256 threads, 4-split reduction + cell update.
__device__ __forceinline__ void gate_tasks(const float* __restrict__ sm,
                                           const float* __restrict__ gbase,
                                           const float* __restrict__ bias,
                                           float* __restrict__ Hdst,
                                           float creg[2], int tid,
                                           bool withx, float x)
{
    #pragma unroll
    for (int rep = 0; rep < 2; ++rep) {
        int tt = tid + rep*NT;
        if (tt < 8*H) {
            int b = tt & 7, hu = tt >> 3;
            const float* gp = gbase + b*GROW + 4*hu;
            float4 s0 = *reinterpret_cast<const float4*>(gp);
            float4 s1 = *reinterpret_cast<const float4*>(gp + SZ_G);
            float4 s2 = *reinterpret_cast<const float4*>(gp + 2*SZ_G);
            float4 s3 = *reinterpret_cast<const float4*>(gp + 3*SZ_G);
            float4 bb = *reinterpret_cast<const float4*>(bias + 4*hu);
            float gi = (s0.x+s1.x)+(s2.x+s3.x) + bb.x;
            float gf = (s0.y+s1.y)+(s2.y+s3.y) + bb.y;
            float gg = (s0.z+s1.z)+(s2.z+s3.z) + bb.z;
            float go = (s0.w+s1.w)+(s2.w+s3.w) + bb.w;
            if (withx) {
                float4 wx = *reinterpret_cast<const float4*>(sm + OFF_WX + 4*hu);
                gi = fmaf(x, wx.x, gi);
                gf = fmaf(x, wx.y, gf);
                gg = fmaf(x, wx.z, gg);
                go = fmaf(x, wx.w, go);
            }
            float hn = cellup(gi, gf, gg, go, creg[rep]);
            Hdst[b*HR + hu] = hn;
        }
    }
}

__device__ __forceinline__ void out_reduce(const float* __restrict__ sm,
                                           const float* __restrict__ H2,
                                           float* __restrict__ smw,
                                           float* __restrict__ out,
                                           int wid, int lane, int b0, int tp,
                                           bool feed)
{
    const float* h2p = H2 + wid*HR;
    float p = h2p[lane] * sm[OFF_WL + lane];
    if (lane + 32 < H) p += h2p[lane + 32] * sm[OFF_WL + lane + 32];
    #pragma unroll
    for (int o = 16; o > 0; o >>= 1)
        p += __shfl_xor_sync(0xffffffffu, p, o);
    if (lane == 0) {
        float ov = p + sm[OFF_BL];
        out[(b0 + wid)*TTOT + tp] = ov;
        if (feed) smw[wid] = ov;
    }
}

__global__ void __launch_bounds__(NT)
lstm_seq_kernel(const float* __restrict__ input,
                const float* __restrict__ Wih1, const float* __restrict__ Whh1,
                const float* __restrict__ bih1, const float* __restrict__ bhh1,
                const float* __restrict__ Wih2, const float* __restrict__ Whh2,
                const float* __restrict__ bih2, const float* __restrict__ bhh2,
                const float* __restrict__ Wl,   const float* __restrict__ bl,
                float* __restrict__ out)
{
    extern __shared__ __align__(16) float sm[];
    const int tid = threadIdx.x;
    const int b0  = blockIdx.x * 8;

    // ---------- one-time prep: k-pair-interleaved weights ----------
    // W1P float at kp*WROW + 2j + p = Whh1[rowOf(j)][2kp+p]
    for (int idx = tid; idx < SZ_W1P; idx += NT) {
        int kp = idx / WROW, r = idx % WROW;
        int j = r >> 1, p = r & 1;
        int u = j >> 2, g = j & 3;
        int k = 2*kp + p;
        sm[OFF_W1P + idx] = (u < H && k < H) ? Whh1[(g*H + u)*H + k] : 0.0f;
    }
    // W2P: k 0..50 = Wih2, 52..102 = Whh2 (51,103 pads)
    for (int idx = tid; idx < SZ_W2P; idx += NT) {
        int kp = idx / WROW, r = idx % WROW;
        int j = r >> 1, p = r & 1;
        int u = j >> 2, g = j & 3;
        int k = 2*kp + p;
        float v = 0.0f;
        if (u < H) {
            int row = (g*H + u)*H;
            if (k < H)                   v = Wih2[row + k];
            else if (k >= 52 && k < 103) v = Whh2[row + (k - 52)];
        }
        sm[OFF_W2P + idx] = v;
    }
    for (int j = tid; j < GP; j += NT) {
        int u = j >> 2, g = j & 3;
        float wx = 0.f, v1 = 0.f, v2 = 0.f;
        if (u < H) {
            int row = g*H + u;
            wx = Wih1[row];
            v1 = bih1[row] + bhh1[row];
            v2 = bih2[row] + bhh2[row];
        }
        sm[OFF_WX + j] = wx;
        sm[OFF_B1 + j] = v1;
        sm[OFF_B2 + j] = v2;
    }
    if (tid < 64) sm[OFF_WL + tid] = (tid < H) ? Wl[tid] : 0.0f;
    for (int idx = tid; idx < 8*TSEQ; idx += NT) {
        int b = idx >> 9, tt = idx & 511;
        sm[OFF_IN + b*INROW + tt] = input[b0*TSEQ + idx];
    }
    for (int idx = tid; idx < 16*HR; idx += NT) sm[OFF_H1 + idx] = 0.0f;
    for (int idx = tid; idx < 8*SZ_G; idx += NT) sm[OFF_G1 + idx] = 0.0f;
    if (tid < 8)  sm[OFF_OUT + tid] = 0.0f;
    if (tid == 0) sm[OFF_BL] = bl[0];
    __syncthreads();

    // ---------- roles ----------
    const int wid  = tid >> 5, lane = tid & 31;
    const int js   = wid & 1;                 // j-slice (2 x 26 units)
    const int kh   = wid >> 1;                // k-split (0..3)
    const bool mact = (lane < 26);
    const int j0   = 4*(js*26 + lane);        // 4 cols = one unit's (i,f,g,o)

    // load-balanced quad windows: mv2 {7,6,7,6}Q, mv1 {3,4,3,4}Q => 20 kp/warp
    const int w2kp0[4] = {0, 14, 26, 40};
    const int h2off[4] = {0, 28,  0, 28};
    const int w1kp0[4] = {0,  6, 14, 20};
    const int h1off[4] = {0, 12, 28, 40};

    float* H1 = sm + OFF_H1;
    float* H2 = sm + OFF_H2;
    const float* w2p = sm + OFF_W2P + w2kp0[kh]*WROW;
    const float* w1p = sm + OFF_W1P + w1kp0[kh]*WROW;
    const float* h2b = ((kh < 2) ? H1 : H2) + h2off[kh];
    const float* h1b = H1 + h1off[kh];
    float* g1out = sm + OFF_G1 + kh*SZ_G;
    float* g2out = sm + OFF_G2 + kh*SZ_G;

    float c1r[2] = {0.f, 0.f};
    float c2r[2] = {0.f, 0.f};
    const int gb = tid & 7;

    for (int t = 0; t < TTOT; ++t) {
        // future-only pre-phase: g2(t-1) then out(t-1) so x(t) exists
        if (t >= TSEQ) {
            gate_tasks(sm, sm + OFF_G2, sm + OFF_B2, H2, c2r, tid, false, 0.f);
            __syncthreads();
            out_reduce(sm, H2, sm + OFF_OUT, out, wid, lane, b0, t-1, true);
            __syncthreads();
        }

        // G phase: g1(t) [+ g2(t-1) in main region]
        {
            float x = (t < TSEQ) ? sm[OFF_IN + gb*INROW + t] : sm[OFF_OUT + gb];
            gate_tasks(sm, sm + OFF_G1, sm + OFF_B1, H1, c1r, tid, true, x);
        }
        if (t > 0 && t < TSEQ)
            gate_tasks(sm, sm + OFF_G2, sm + OFF_B2, H2, c2r, tid, false, 0.f);
        __syncthreads();

        // M phase: mv2(t) + mv1(t+1) + out(t-1)
        if (mact) {
            if (kh & 1) {
                mvp<6>(w2p, h2b, g2out, j0);
                mvp<4>(w1p, h1b, g1out, j0);
            } else {
                mvp<7>(w2p, h2b, g2out, j0);
                mvp<3>(w1p, h1b, g1out, j0);
            }
        }
        if (t > 0 && t < TSEQ)
            out_reduce(sm, H2, sm + OFF_OUT, out, wid, lane, b0, t-1, false);
        __syncthreads();
    }

    // epilogue: g2(TTOT-1) + out(TTOT-1)
    gate_tasks(sm, sm + OFF_G2, sm + OFF_B2, H2, c2r, tid, false, 0.f);
    __syncthreads();
    out_reduce(sm, H2, sm + OFF_OUT, out, wid, lane, b0, TTOT-1, false);
}

extern "C" void kernel_launch(void* const* d_in, const int* in_sizes, int n_in,
                              void* d_out, int out_size)
{
    (void)n_in; (void)out_size;
    cudaFuncSetAttribute(lstm_seq_kernel,
                         cudaFuncAttributeMaxDynamicSharedMemorySize, SMEM_BYTES);
    int nblocks = in_sizes[0] / (TSEQ * 8);   // B / 8 = 128
    lstm_seq_kernel<<<nblocks, NT, SMEM_BYTES>>>(
        (const float*)d_in[0],  (const float*)d_in[1], (const float*)d_in[2],
        (const float*)d_in[3],  (const float*)d_in[4], (const float*)d_in[5],
        (const float*)d_in[6],  (const float*)d_in[7], (const float*)d_in[8],
        (const float*)d_in[9],  (const float*)d_in[10],
        (float*)d_out);
}

// round 11
// speedup vs baseline: 1.0809x; 1.0809x over previous
#include <cuda_runtime.h>
#include <cstdint>

typedef unsigned long long ull;

#define H     51
#define GP    208         // gate cols (204 real, interleaved col = 4u+g)
#define GROW  216         // per-batch gate row stride (conflict-free, mod32 clean)
#define SZ_G  (4*GROW)    // 864 per split buffer (4 batches per group)
#define HR    72          // h row stride (conflict-free stores: 72 mod 32 = 8)
#define TSEQ  512
#define FUT   64
#define TTOT  (TSEQ + FUT)
#define NT    512         // two groups of 256 (8 warps each)
#define NG    256
#define INROW 516
#define WROW  416         // k-pair weight row: 208 cols x 2 parities

// ---- smem layout (float offsets) ----
#define OFF_W1P 0                         // 28 kp-rows x 416 (shared)
#define SZ_W1P  (28*WROW)
#define OFF_W2P (OFF_W1P + SZ_W1P)        // 52 kp-rows x 416 (shared)
#define SZ_W2P  (52*WROW)
#define OFF_WX  (OFF_W2P + SZ_W2P)
#define OFF_B1  (OFF_WX + GP)
#define OFF_B2  (OFF_B1 + GP)
#define OFF_WL  (OFF_B2 + GP)             // 64
#define OFF_GRP (OFF_WL + 64)             // 33968
// per-group relative offsets
#define GIN   0                           // 4 x 516
#define GH1   (GIN + 4*INROW)             // 2064
#define GH2   (GH1 + 4*HR)                // 2352
#define GG1   (GH2 + 4*HR)                // 2640
#define GG2   (GG1 + 4*SZ_G)              // 6096
#define GOUT  (GG2 + 4*SZ_G)              // 9552
#define GRP   (GOUT + 8)                  // 9560
#define OFF_BL (OFF_GRP + 2*GRP)
#define SMEM_FLOATS (OFF_BL + 4)          // 53092 -> 212368 B
#define SMEM_BYTES  (SMEM_FLOATS * 4)

#define GBAR(id) asm volatile("bar.sync %0, %1;" :: "r"(id), "r"(NG) : "memory")

__device__ __forceinline__ ull ffma2(ull a, ull b, ull c) {
    ull d;
    asm("fma.rn.f32x2 %0, %1, %2, %3;" : "=l"(d) : "l"(a), "l"(b), "l"(c));
    return d;
}

__device__ __forceinline__ float foldadd(ull a) {
    float lo, hi;
    asm("mov.b64 {%0,%1}, %2;" : "=f"(lo), "=f"(hi) : "l"(a));
    return lo + hi;
}

__device__ __forceinline__ float fex2(float x) {
    float r;
    asm("ex2.approx.f32 %0, %1;" : "=f"(r) : "f"(x));
    return r;
}

__device__ __forceinline__ float frcp(float x) {
    float r;
    asm("rcp.approx.f32 %0, %1;" : "=f"(r) : "f"(x));
    return r;
}

// LSTM cell update, 5 EX2 + 2 RCP (R8/R10-validated, rel err ~2.3e-7).
__device__ __forceinline__ float cellup(float gi, float gf, float gg, float go,
                                        float& c)
{
    const float L2E = 1.4426950408889634f;
    float ei = fex2(-L2E * gi);
    float ef = fex2(-L2E * gf);
    float eg = fex2(-2.0f * L2E * fabsf(gg));
    float pi = 1.0f + ei, pf = 1.0f + ef, pg = 1.0f + eg;
    float tg = copysignf(1.0f - eg, gg);
    float num = c * pi * pg + tg * pf;
    c = num * frcp(pf * pi * pg);
    float eo = fex2(-L2E * go);
    float ec = fex2(-2.0f * L2E * fabsf(c));
    return copysignf(1.0f - ec, c) * frcp((1.0f + eo) * (1.0f + ec));
}

// Dense-lane k-parity matvec over NQ quads, 4 batches.
// Lane owns cols {j0a,j0a+1} and {j0b,j0b+1}; every weight LDS.128 is
// 16B/lane dense (4 wf). h loaded plain (no duplication).
template<int NQ>
__device__ __forceinline__ void mvp4(const float* __restrict__ wp,
                                     const float* __restrict__ hb,
                                     float* __restrict__ gout,
                                     int j0a, int j0b)
{
    ull acc[4][4];
    #pragma unroll
    for (int b = 0; b < 4; ++b) {
        #pragma unroll
        for (int c = 0; c < 4; ++c) acc[b][c] = 0ull;
    }
    #pragma unroll
    for (int q = 0; q < NQ; ++q) {
        const float* ra = wp + (2*q  )*WROW;   // k-pair 2q   (h .x)
        const float* rb = wp + (2*q+1)*WROW;   // k-pair 2q+1 (h .y)
        ulonglong2 waA = *reinterpret_cast<const ulonglong2*>(ra + 2*j0a);
        ulonglong2 waB = *reinterpret_cast<const ulonglong2*>(ra + 2*j0b);
        ulonglong2 wbA = *reinterpret_cast<const ulonglong2*>(rb + 2*j0a);
        ulonglong2 wbB = *reinterpret_cast<const ulonglong2*>(rb + 2*j0b);
        #pragma unroll
        for (int b = 0; b < 4; ++b) {
            ulonglong2 hv = *reinterpret_cast<const ulonglong2*>(hb + b*HR + 4*q);
            acc[b][0] = ffma2(waA.x, hv.x, acc[b][0]);
            acc[b][1] = ffma2(waA.y, hv.x, acc[b][1]);
            acc[b][2] = ffma2(waB.x, hv.x, acc[b][2]);
            acc[b][3] = ffma2(waB.y, hv.x, acc[b][3]);
            acc[b][0] = ffma2(wbA.x, hv.y, acc[b][0]);
            acc[b][1] = ffma2(wbA.y, hv.y, acc[b][1]);
            acc[b][2] = ffma2(wbB.x, hv.y, acc[b][2]);
            acc[b][3] = ffma2(wbB.y, hv.y, acc[b][3]);
        }
    }
    #pragma unroll
    for (int b = 0; b < 4; ++b) {
        float2 rA = make_float2(foldadd(acc[b][0]), foldadd(acc[b][1]));
        float2 rB = make_float2(foldadd(acc[b][2]), foldadd(acc[b][3]));
        *reinterpret_cast<float2*>(gout + b*GROW + j0a) = rA;
        *reinterpret_cast<float2*>(gout + b*GROW + j0b) = rB;
    }
}

// per-group gate tasks: 204 (b,hu) over 256 threads, single rep.
__device__ __forceinline__ void gate_tasks(const float* __restrict__ sm,
                                           const float* __restrict__ gbase,
                                           const float* __restrict__ bias,
                                           float* __restrict__ Hdst,
                                           float& creg, int gt,
                                           bool withx, float x)
{
    if (gt < 4*H) {
        int b = gt & 3, hu = gt >> 2;
        const float* gp = gbase + b*GROW + 4*hu;
        float4 s0 = *reinterpret_cast<const float4*>(gp);
        float4 s1 = *reinterpret_cast<const float4*>(gp + SZ_G);
        float4 s2 = *reinterpret_cast<const float4*>(gp + 2*SZ_G);
        float4 s3 = *reinterpret_cast<const float4*>(gp + 3*SZ_G);
        float4 bb = *reinterpret_cast<const float4*>(bias + 4*hu);
        float gi = (s0.x+s1.x)+(s2.x+s3.x) + bb.x;
        float gf = (s0.y+s1.y)+(s2.y+s3.y) + bb.y;
        float gg = (s0.z+s1.z)+(s2.z+s3.z) + bb.z;
        float go = (s0.w+s1.w)+(s2.w+s3.w) + bb.w;
        if (withx) {
            float4 wx = *reinterpret_cast<const float4*>(sm + OFF_WX + 4*hu);
            gi = fmaf(x, wx.x, gi);
            gf = fmaf(x, wx.y, gf);
            gg = fmaf(x, wx.z, gg);
            go = fmaf(x, wx.w, go);
        }
        float hn = cellup(gi, gf, gg, go, creg);
        Hdst[b*HR + hu] = hn;
    }
}

// per-group output reduce: warps 0-3 of the group handle batch = wid.
__device__ __forceinline__ void out_reduce(const float* __restrict__ sm,
                                           const float* __restrict__ H2,
                                           float* __restrict__ outs,
                                           float* __restrict__ out,
                                           int wid, int lane, int bglob, int tp,
                                           bool feed)
{
    if (wid < 4) {
        const float* h2p = H2 + wid*HR;
        float p = h2p[lane] * sm[OFF_WL + lane];
        if (lane + 32 < H) p += h2p[lane + 32] * sm[OFF_WL + lane + 32];
        #pragma unroll
        for (int o = 16; o > 0; o >>= 1)
            p += __shfl_xor_sync(0xffffffffu, p, o);
        if (lane == 0) {
            float ov = p + sm[OFF_BL];
            out[(bglob + wid)*TTOT + tp] = ov;
            if (feed) outs[wid] = ov;
        }
    }
}

__global__ void __launch_bounds__(NT, 1)
lstm_seq_kernel(const float* __restrict__ input,
                const float* __restrict__ Wih1, const float* __restrict__ Whh1,
                const float* __restrict__ bih1, const float* __restrict__ bhh1,
                const float* __restrict__ Wih2, const float* __restrict__ Whh2,
                const float* __restrict__ bih2, const float* __restrict__ bhh2,
                const float* __restrict__ Wl,   const float* __restrict__ bl,
                float* __restrict__ out)
{
    extern __shared__ __align__(16) float sm[];
    const int tid = threadIdx.x;
    const int cb0 = blockIdx.x * 8;

    // ---------- one-time prep (all 512 threads) ----------
    // k-pair-interleaved weights: float at kp*WROW + 2j + p = W[rowOf(j)][2kp+p]
    for (int idx = tid; idx < SZ_W1P; idx += NT) {
        int kp = idx / WROW, r = idx % WROW;
        int j = r >> 1, p = r & 1;
        int u = j >> 2, g = j & 3;
        int k = 2*kp + p;
        sm[OFF_W1P + idx] = (u < H && k < H) ? Whh1[(g*H + u)*H + k] : 0.0f;
    }
    for (int idx = tid; idx < SZ_W2P; idx += NT) {
        int kp = idx / WROW, r = idx % WROW;
        int j = r >> 1, p = r & 1;
        int u = j >> 2, g = j & 3;
        int k = 2*kp + p;
        float v = 0.0f;
        if (u < H) {
            int row = (g*H + u)*H;
            if (k < H)                   v = Wih2[row + k];
            else if (k >= 52 && k < 103) v = Whh2[row + (k - 52)];
        }
        sm[OFF_W2P + idx] = v;
    }
    for (int j = tid; j < GP; j += NT) {
        int u = j >> 2, g = j & 3;
        float wx = 0.f, v1 = 0.f, v2 = 0.f;
        if (u < H) {
            int row = g*H + u;
            wx = Wih1[row];
            v1 = bih1[row] + bhh1[row];
            v2 = bih2[row] + bhh2[row];
        }
        sm[OFF_WX + j] = wx;
        sm[OFF_B1 + j] = v1;
        sm[OFF_B2 + j] = v2;
    }
    if (tid < 64) sm[OFF_WL + tid] = (tid < H) ? Wl[tid] : 0.0f;
    for (int idx = tid; idx < 8*TSEQ; idx += NT) {
        int b = idx >> 9, tt = idx & 511;
        sm[OFF_GRP + (b >> 2)*GRP + GIN + (b & 3)*INROW + tt]
            = input[cb0*TSEQ + idx];
    }
    for (int idx = tid; idx < 2*(GRP - GH1); idx += NT) {
        int g = idx / (GRP - GH1), r = idx % (GRP - GH1);
        sm[OFF_GRP + g*GRP + GH1 + r] = 0.0f;
    }
    if (tid == 0) sm[OFF_BL] = bl[0];
    __syncthreads();

    // ---------- group roles ----------
    const int g    = tid >> 8;              // 0 / 1
    const int gt   = tid & 255;             // in-group tid
    const int bar  = 1 + g;                 // named barrier id
    const int bglob = cb0 + g*4;            // global batch base for this group
    float* SG  = sm + OFF_GRP + g*GRP;
    float* H1  = SG + GH1;
    float* H2  = SG + GH2;
    float* G1b = SG + GG1;
    float* G2b = SG + GG2;
    float* OUTS = SG + GOUT;

    const int wid  = gt >> 5, lane = gt & 31;
    const int js   = wid & 1;               // j-slice (2 x 52 cols per region)
    const int kh   = wid >> 1;              // k-split (0..3)
    const bool mact = (lane < 26);
    const int j0a  = js*104 + 2*lane;       // cols j0a, j0a+1
    const int j0b  = j0a + 52;              // cols j0b, j0b+1

    // quad windows: mv2 {7,6,7,6}Q, mv1 {3,4,3,4}Q
    const int w2kp0[4] = {0, 14, 26, 40};
    const int h2off[4] = {0, 28,  0, 28};
    const int w1kp0[4] = {0,  6, 14, 20};
    const int h1off[4] = {0, 12, 28, 40};

    const float* w2p = sm + OFF_W2P + w2kp0[kh]*WROW;
    const float* w1p = sm + OFF_W1P + w1kp0[kh]*WROW;
    const float* h2b = ((kh < 2) ? H1 : H2) + h2off[kh];
    const float* h1b = H1 + h1off[kh];
    float* g1out = G1b + kh*SZ_G;
    float* g2out = G2b + kh*SZ_G;

    float c1 = 0.f, c2 = 0.f;
    const int xb = gt & 3;                  // gate-task batch for x reads

    for (int t = 0; t < TTOT; ++t) {
        // future-only pre-phase: g2(t-1), out(t-1) so x(t) exists
        if (t >= TSEQ) {
            gate_tasks(sm, G2b, sm + OFF_B2, H2, c2, gt, false, 0.f);
            GBAR(bar);
            out_reduce(sm, H2, OUTS, out, wid, lane, bglob, t-1, true);
            GBAR(bar);
        }

        // G phase: g1(t) [+ g2(t-1) in main region]
        {
            float x = (t < TSEQ) ? SG[GIN + xb*INROW + t] : OUTS[xb];
            gate_tasks(sm, G1b, sm + OFF_B1, H1, c1, gt, true, x);
        }
        if (t > 0 && t < TSEQ)
            gate_tasks(sm, G2b, sm + OFF_B2, H2, c2, gt, false, 0.f);
        GBAR(bar);

        // M phase: mv2(t) + mv1(t+1) + out(t-1)
        if (mact) {
            if (kh & 1) {
                mvp4<6>(w2p, h2b, g2out, j0a, j0b);
                mvp4<4>(w1p, h1b, g1out, j0a, j0b);
            } else {
                mvp4<7>(w2p, h2b, g2out, j0a, j0b);
                mvp4<3>(w1p, h1b, g1out, j0a, j0b);
            }
        }
        if (t > 0 && t < TSEQ)
            out_reduce(sm, H2, OUTS, out, wid, lane, bglob, t-1, false);
        GBAR(bar);
    }

    // epilogue: g2(TTOT-1) + out(TTOT-1)
    gate_tasks(sm, G2b, sm + OFF_B2, H2, c2, gt, false, 0.f);
    GBAR(bar);
    out_reduce(sm, H2, OUTS, out, wid, lane, bglob, TTOT-1, false);
}

extern "C" void kernel_launch(void* const* d_in, const int* in_sizes, int n_in,
                              void* d_out, int out_size)
{
    (void)n_in; (void)out_size;
    cudaFuncSetAttribute(lstm_seq_kernel,
                         cudaFuncAttributeMaxDynamicSharedMemorySize, SMEM_BYTES);
    int nblocks = in_sizes[0] / (TSEQ * 8);   // B / 8 = 128
    lstm_seq_kernel<<<nblocks, NT, SMEM_BYTES>>>(
        (const float*)d_in[0],  (const float*)d_in[1], (const float*)d_in[2],
        (const float*)d_in[3],  (const float*)d_in[4], (const float*)d_in[5],
        (const float*)d_in[6],  (const float*)d_in[7], (const float*)d_in[8],
        (const float*)d_in[9],  (const float*)d_in[10],
        (float*)d_out);
}

// round 13
// speedup vs baseline: 1.2322x; 1.1399x over previous
#include <cuda_runtime.h>
#include <cstdint>

typedef unsigned long long ull;

#define H     51
#define TSEQ  512
#define FUT   64
#define TTOT  (TSEQ + FUT)
#define NT    256          // 8 warps = 2 groups x 4 warps
#define HRS   56           // h row stride (52 used)
#define INROW 516
#define WR    416          // weight kp-row: [A:52u x 4][B:52u x 4] k-parity packed

// ---- smem layout (float offsets) ----
#define OFF_W1  0                   // 26 kp-rows (K=52)
#define SZ_W1   (26*WR)             // 10816
#define OFF_W2  (OFF_W1 + SZ_W1)    // 52 kp-rows (K=104: h1 | h2)
#define SZ_W2   (52*WR)             // 21632
#define OFF_WX  (OFF_W2 + SZ_W2)    // 256 (padded)
#define OFF_B1  (OFF_WX + 256)
#define OFF_B2  (OFF_B1 + 256)
#define OFF_WL  (OFF_B2 + 256)      // 64 (bl stashed at +63, single writer)
#define OFF_GRP (OFF_WL + 64)
// per-group offsets
#define GIN     0                   // 4 x 516
#define GH1     (4*INROW)           // 2 parities x 4 b x HRS
#define GH2     (GH1 + 2*4*HRS)
#define GRPSZ   (GH2 + 2*4*HRS)     // 2960
#define SMEM_FLOATS (OFF_GRP + 2*GRPSZ)
#define SMEM_BYTES  (SMEM_FLOATS * 4)

__device__ __forceinline__ ull ffma2(ull a, ull b, ull c) {
    ull d;
    asm("fma.rn.f32x2 %0, %1, %2, %3;" : "=l"(d) : "l"(a), "l"(b), "l"(c));
    return d;
}

__device__ __forceinline__ float foldadd(ull a) {
    float lo, hi;
    asm("mov.b64 {%0,%1}, %2;" : "=f"(lo), "=f"(hi) : "l"(a));
    return lo + hi;
}

__device__ __forceinline__ float fex2(float x) {
    float r; asm("ex2.approx.f32 %0, %1;" : "=f"(r) : "f"(x)); return r;
}
__device__ __forceinline__ float frcp(float x) {
    float r; asm("rcp.approx.f32 %0, %1;" : "=f"(r) : "f"(x)); return r;
}

// LSTM cell update, 5 EX2 + 2 RCP (R8/R10/R11-validated, rel err ~2.3e-7).
__device__ __forceinline__ float cellup(float gi, float gf, float gg, float go,
                                        float& c)
{
    const float L2E = 1.4426950408889634f;
    float ei = fex2(-L2E * gi);
    float ef = fex2(-L2E * gf);
    float eg = fex2(-2.0f * L2E * fabsf(gg));
    float pi = 1.0f + ei, pf = 1.0f + ef, pg = 1.0f + eg;
    float tg = copysignf(1.0f - eg, gg);
    float num = c * pi * pg + tg * pf;
    c = num * frcp(pf * pi * pg);
    float eo = fex2(-L2E * go);
    float ec = fex2(-2.0f * L2E * fabsf(c));
    return copysignf(1.0f - ec, c) * frcp((1.0f + eo) * (1.0f + ec));
}

// Full-K matvec slice: NQ quads, lane owns 4 cols (one unit), 4 batches.
// acc[b][c] = f32x2 (even-k, odd-k) partials. Per quad: 4 dense weight
// LDS.128 (16B/lane) + 4 broadcast h LDS.128 -> 32 FFMA2; 16 indep chains.
template<int NQ>
__device__ __forceinline__ void mv13(const float* __restrict__ wpl,
                                     const float* __restrict__ hb,
                                     ull acc[4][4])
{
    #pragma unroll
    for (int q = 0; q < NQ; ++q) {
        const float* r0 = wpl + (2*q  )*WR;
        const float* r1 = wpl + (2*q+1)*WR;
        ulonglong2 wA0 = *reinterpret_cast<const ulonglong2*>(r0);
        ulonglong2 wB0 = *reinterpret_cast<const ulonglong2*>(r0 + 208);
        ulonglong2 wA1 = *reinterpret_cast<const ulonglong2*>(r1);
        ulonglong2 wB1 = *reinterpret_cast<const ulonglong2*>(r1 + 208);
        #pragma unroll
        for (int b = 0; b < 4; ++b) {
            ulonglong2 hv = *reinterpret_cast<const ulonglong2*>(hb + b*HRS + 4*q);
            acc[b][0] = ffma2(wA0.x, hv.x, acc[b][0]);
            acc[b][1] = ffma2(wA0.y, hv.x, acc[b][1]);
            acc[b][2] = ffma2(wB0.x, hv.x, acc[b][2]);
            acc[b][3] = ffma2(wB0.y, hv.x, acc[b][3]);
            acc[b][0] = ffma2(wA1.x, hv.y, acc[b][0]);
            acc[b][1] = ffma2(wA1.y, hv.y, acc[b][1]);
            acc[b][2] = ffma2(wB1.x, hv.y, acc[b][2]);
            acc[b][3] = ffma2(wB1.y, hv.y, acc[b][3]);
        }
    }
}

__device__ __forceinline__ void zacc(ull acc[4][4]) {
    #pragma unroll
    for (int b = 0; b < 4; ++b) {
        #pragma unroll
        for (int c = 0; c < 4; ++c) acc[b][c] = 0ull;
    }
}

// fused gate tail: fold parities, bias (+x*wx), cellup, store plain h.
__device__ __forceinline__ void gtail(ull acc[4][4], float cst[4],
                                      const float* __restrict__ bp,
                                      const float* __restrict__ wxp,
                                      const float* __restrict__ xv, bool withx,
                                      float* __restrict__ hdst, int uglob,
                                      bool act)
{
    if (!act) return;
    float4 bb = *reinterpret_cast<const float4*>(bp);
    float4 wx = withx ? *reinterpret_cast<const float4*>(wxp)
                      : make_float4(0.f, 0.f, 0.f, 0.f);
    #pragma unroll
    for (int b = 0; b < 4; ++b) {
        float gi = foldadd(acc[b][0]) + bb.x;
        float gf = foldadd(acc[b][1]) + bb.y;
        float gg = foldadd(acc[b][2]) + bb.z;
        float go = foldadd(acc[b][3]) + bb.w;
        if (withx) {
            gi = fmaf(xv[b], wx.x, gi);
            gf = fmaf(xv[b], wx.y, gf);
            gg = fmaf(xv[b], wx.z, gg);
            go = fmaf(xv[b], wx.w, go);
        }
        float hn = cellup(gi, gf, gg, go, cst[b]);
        hdst[b*HRS + uglob] = hn;
    }
}

// h2 . Wl reduce for one batch; result valid in ALL lanes (xor reduce).
__device__ __forceinline__ float outred(const float* __restrict__ h2row,
                                        const float* __restrict__ wl, int lane)
{
    float p = h2row[lane] * wl[lane];
    if (lane + 32 < H) p += h2row[lane + 32] * wl[lane + 32];
    #pragma unroll
    for (int o = 16; o > 0; o >>= 1)
        p += __shfl_xor_sync(0xffffffffu, p, o);
    return p;
}

__global__ void __launch_bounds__(NT, 1)
lstm_seq_kernel(const float* __restrict__ input,
                const float* __restrict__ Wih1, const float* __restrict__ Whh1,
                const float* __restrict__ bih1, const float* __restrict__ bhh1,
                const float* __restrict__ Wih2, const float* __restrict__ Whh2,
                const float* __restrict__ bih2, const float* __restrict__ bhh2,
                const float* __restrict__ Wl,   const float* __restrict__ bl,
                float* __restrict__ out)
{
    extern __shared__ __align__(16) float sm[];
    const int tid = threadIdx.x;
    const int cb0 = blockIdx.x * 8;

    // ---------- one-time prep ----------
    // weight kp-row layout: [A: u=0..51, 4 floats (c0e,c0o,c1e,c1o)]
    //                       [B: u=0..51, 4 floats (c2e,c2o,c3e,c3o)]
    // col j = 4u + c  <->  orig row = c*H + u (PyTorch gate order i,f,g,o)
    for (int idx = tid; idx < SZ_W1; idx += NT) {
        int kp = idx / WR, r = idx % WR;
        int part = (r >= 208) ? 1 : 0, rr = r - part*208;
        int u = rr >> 2, q = rr & 3;
        int c = part*2 + (q >> 1), par = q & 1;
        int k = 2*kp + par;
        sm[OFF_W1 + idx] = (u < H && k < H) ? Whh1[(c*H + u)*H + k] : 0.0f;
    }
    for (int idx = tid; idx < SZ_W2; idx += NT) {
        int kp = idx / WR, r = idx % WR;
        int part = (r >= 208) ? 1 : 0, rr = r - part*208;
        int u = rr >> 2, q = rr & 3;
        int c = part*2 + (q >> 1), par = q & 1;
        int k = 2*kp + par;          // 0..103: [h1 52 | h2 52]
        float v = 0.0f;
        if (u < H) {
            int row = (c*H + u)*H;
            if (k < H)                   v = Wih2[row + k];
            else if (k >= 52 && k < 103) v = Whh2[row + (k - 52)];
        }
        sm[OFF_W2 + idx] = v;
    }
    for (int j = tid; j < 256; j += NT) {
        int u = j >> 2, c = j & 3;
        float wx = 0.f, v1 = 0.f, v2 = 0.f;
        if (u < H && j < 208) {
            int row = c*H + u;
            wx = Wih1[row];
            v1 = bih1[row] + bhh1[row];
            v2 = bih2[row] + bhh2[row];
        }
        sm[OFF_WX + j] = wx;
        sm[OFF_B1 + j] = v1;
        sm[OFF_B2 + j] = v2;
    }
    // single writer per WL slot: 0..50 = Wl, 51..62 = 0, 63 = bl[0]
    if (tid < 64)
        sm[OFF_WL + tid] = (tid < H) ? Wl[tid]
                          : (tid == 63 ? bl[0] : 0.0f);
    for (int idx = tid; idx < 8*TSEQ; idx += NT) {
        int b = idx >> 9, tt = idx & 511;
        sm[OFF_GRP + (b >> 2)*GRPSZ + GIN + (b & 3)*INROW + tt]
            = input[cb0*TSEQ + idx];
    }
    for (int idx = tid; idx < 2*(GRPSZ - GH1); idx += NT) {
        int g = idx / (GRPSZ - GH1), r = idx % (GRPSZ - GH1);
        sm[OFF_GRP + g*GRPSZ + GH1 + r] = 0.0f;
    }
    __syncthreads();

    // ---------- roles ----------
    const int wid  = tid >> 5, lane = tid & 31;
    const int g    = wid >> 2;                    // group 0/1
    const int r4   = wid & 3;
    const int role = g ? (3 - r4) : r4;           // SMSP gets 1 heavy + 1 light
    const bool ismv2 = (role < 2);
    const int uh   = ismv2 ? role : (role - 2);   // unit-half
    const int uglob = uh*26 + lane;               // unit (lanes >=26 inactive)
    const bool act = (lane < 26);
    const int barid = 1 + g;

    float* SG = sm + OFF_GRP + g*GRPSZ;
    float* h1b0 = SG + GH1;
    float* h1b1 = SG + GH1 + 4*HRS;
    float* h2b0 = SG + GH2;
    float* h2b1 = SG + GH2 + 4*HRS;
    const float* wl = sm + OFF_WL;
    const float blv = sm[OFF_WL + 63];

    const float* w2p = sm + OFF_W2 + uglob*4;
    const float* w1p = sm + OFF_W1 + uglob*4;
    const float* b2p = sm + OFF_B2 + 4*uglob;
    const float* b1p = sm + OFF_B1 + 4*uglob;
    const float* wxp = sm + OFF_WX + 4*uglob;
    const int bgl = cb0 + g*4;

    float cst[4] = {0.f, 0.f, 0.f, 0.f};    // c2 (mv2 warps) / c1 (mv1 warps)

    #define GBAR() asm volatile("bar.sync %0, %1;" :: "r"(barid), "r"(128) : "memory")

    // ---------- prologue: mv1(0) + g1(0) ----------
    if (!ismv2) {
        ull acc[4][4]; zacc(acc);
        mv13<13>(w1p, h1b1, acc);            // h1(-1) = 0
        float xv[4];
        #pragma unroll
        for (int b = 0; b < 4; ++b) xv[b] = SG[GIN + b*INROW];
        gtail(acc, cst, b1p, wxp, xv, true, h1b0, uglob, act);
    }
    GBAR();

    for (int t = 0; t < TTOT; ++t) {
        float* h1w = (((t + 1) & 1) ? h1b1 : h1b0);
        const float* h1r = ((t & 1) ? h1b1 : h1b0);
        float* h2w = ((t & 1) ? h2b1 : h2b0);
        const float* h2r = (((t + 1) & 1) ? h2b1 : h2b0);   // h2(t-1)

        if (t < TSEQ - 1) {
            // ===== main region: ONE fat phase =====
            if (ismv2) {
                ull acc[4][4]; zacc(acc);
                mv13<13>(w2p, h1r, acc);             // Wih2 @ h1(t)
                mv13<13>(w2p + 26*WR, h2r, acc);     // Whh2 @ h2(t-1)
                gtail(acc, cst, b2p, 0, 0, false, h2w, uglob, act);
            } else {
                if (t > 0) {                          // out(t-1), 2 batches/warp
                    int bb = (role - 2)*2;
                    float p0 = outred(h2r + bb*HRS, wl, lane);
                    float p1 = outred(h2r + (bb + 1)*HRS, wl, lane);
                    if (lane == 0) {
                        out[(bgl + bb    )*TTOT + (t - 1)] = p0 + blv;
                        out[(bgl + bb + 1)*TTOT + (t - 1)] = p1 + blv;
                    }
                }
                ull acc[4][4]; zacc(acc);
                mv13<13>(w1p, h1r, acc);             // Whh1 @ h1(t)
                float xv[4];
                #pragma unroll
                for (int b = 0; b < 4; ++b)
                    xv[b] = SG[GIN + b*INROW + (t + 1)];
                gtail(acc, cst, b1p, wxp, xv, true, h1w, uglob, act);
            }
            GBAR();
        } else {
            // ===== future-style step (out(t) feeds x(t+1)) =====
            // sub-A: mv2(t)+g2(t);  boundary-gap out(TSEQ-2)
            if (ismv2) {
                ull acc[4][4]; zacc(acc);
                mv13<13>(w2p, h1r, acc);
                mv13<13>(w2p + 26*WR, h2r, acc);
                gtail(acc, cst, b2p, 0, 0, false, h2w, uglob, act);
            } else if (t == TSEQ - 1) {
                int bb = (role - 2)*2;
                float p0 = outred(h2r + bb*HRS, wl, lane);
                float p1 = outred(h2r + (bb + 1)*HRS, wl, lane);
                if (lane == 0) {
                    out[(bgl + bb    )*TTOT + (t - 1)] = p0 + blv;
                    out[(bgl + bb + 1)*TTOT + (t - 1)] = p1 + blv;
                }
            }
            GBAR();
            // sub-B: out(t) (all lanes get value), then mv1(t+1)+g1(t+1)
            if (!ismv2) {
                float xv[4];
                #pragma unroll
                for (int b = 0; b < 4; ++b)
                    xv[b] = outred(h2w + b*HRS, wl, lane) + blv;
                if (role == 2 && lane == 0) {
                    #pragma unroll
                    for (int b = 0; b < 4; ++b)
                        out[(bgl + b)*TTOT + t] = xv[b];
                }
                if (t + 1 < TTOT) {
                    ull acc[4][4]; zacc(acc);
                    mv13<13>(w1p, h1r, acc);
                    gtail(acc, cst, b1p, wxp, xv, true, h1w, uglob, act);
                }
            }
            GBAR();
        }
    }
    #undef GBAR
}

extern "C" void kernel_launch(void* const* d_in, const int* in_sizes, int n_in,
                              void* d_out, int out_size)
{
    (void)n_in; (void)out_size;
    cudaFuncSetAttribute(lstm_seq_kernel,
                         cudaFuncAttributeMaxDynamicSharedMemorySize, SMEM_BYTES);
    int nblocks = in_sizes[0] / (TSEQ * 8);   // B / 8 = 128
    lstm_seq_kernel<<<nblocks, NT, SMEM_BYTES>>>(
        (const float*)d_in[0],  (const float*)d_in[1], (const float*)d_in[2],
        (const float*)d_in[3],  (const float*)d_in[4], (const float*)d_in[5],
        (const float*)d_in[6],  (const float*)d_in[7], (const float*)d_in[8],
        (const float*)d_in[9],  (const float*)d_in[10],
        (float*)d_out);
}

// round 14
// speedup vs baseline: 1.3129x; 1.0655x over previous
#include <cuda_runtime.h>
#include <cstdint>

typedef unsigned long long ull;

#define H     51
#define TSEQ  512
#define FUT   64
#define TTOT  (TSEQ + FUT)
#define NT    256          // 8 warps = 2 groups x 4 warps
#define HRS   56           // h row stride (52 used)
#define INROW 516
#define WR    416          // weight kp-row: [A:52u x 4][B:52u x 4] k-parity packed
#define NC2   7            // cached quads, mv2 warps (Wih2@h1 stream)
#define NC1   5            // cached quads, mv1 warps (W1 stream)

// ---- smem layout (float offsets) ----
#define OFF_W1  0                   // 26 kp-rows (K=52)
#define SZ_W1   (26*WR)             // 10816
#define OFF_W2  (OFF_W1 + SZ_W1)    // 52 kp-rows (K=104: h1 | h2)
#define SZ_W2   (52*WR)             // 21632
#define OFF_WX  (OFF_W2 + SZ_W2)    // 256 (padded)
#define OFF_B1  (OFF_WX + 256)
#define OFF_B2  (OFF_B1 + 256)
#define OFF_WL  (OFF_B2 + 256)      // 64 (bl stashed at +63, single writer)
#define OFF_GRP (OFF_WL + 64)
// per-group offsets
#define GIN     0                   // 4 x 516
#define GH1     (4*INROW)           // 2 parities x 4 b x HRS
#define GH2     (GH1 + 2*4*HRS)
#define GRPSZ   (GH2 + 2*4*HRS)     // 2960
#define SMEM_FLOATS (OFF_GRP + 2*GRPSZ)
#define SMEM_BYTES  (SMEM_FLOATS * 4)

__device__ __forceinline__ ull ffma2(ull a, ull b, ull c) {
    ull d;
    asm("fma.rn.f32x2 %0, %1, %2, %3;" : "=l"(d) : "l"(a), "l"(b), "l"(c));
    return d;
}

__device__ __forceinline__ float foldadd(ull a) {
    float lo, hi;
    asm("mov.b64 {%0,%1}, %2;" : "=f"(lo), "=f"(hi) : "l"(a));
    return lo + hi;
}

__device__ __forceinline__ float fex2(float x) {
    float r; asm("ex2.approx.f32 %0, %1;" : "=f"(r) : "f"(x)); return r;
}
__device__ __forceinline__ float frcp(float x) {
    float r; asm("rcp.approx.f32 %0, %1;" : "=f"(r) : "f"(x)); return r;
}

// LSTM cell update, 5 EX2 + 2 RCP (validated rel err ~2.3e-7).
__device__ __forceinline__ float cellup(float gi, float gf, float gg, float go,
                                        float& c)
{
    const float L2E = 1.4426950408889634f;
    float ei = fex2(-L2E * gi);
    float ef = fex2(-L2E * gf);
    float eg = fex2(-2.0f * L2E * fabsf(gg));
    float pi = 1.0f + ei, pf = 1.0f + ef, pg = 1.0f + eg;
    float tg = copysignf(1.0f - eg, gg);
    float num = c * pi * pg + tg * pf;
    c = num * frcp(pf * pi * pg);
    float eo = fex2(-L2E * go);
    float ec = fex2(-2.0f * L2E * fabsf(c));
    return copysignf(1.0f - ec, c) * frcp((1.0f + eo) * (1.0f + ec));
}

// Full-K matvec slice: NQ quads, lane owns 4 cols (one unit), 4 batches.
// First NC quads use register-cached weights (no LDS); rest load from smem.
template<int NC, int NQ>
__device__ __forceinline__ void mv13c(const ull cw[][8],
                                      const float* __restrict__ wpl,
                                      const float* __restrict__ hb,
                                      ull acc[4][4])
{
    #pragma unroll
    for (int q = 0; q < NQ; ++q) {
        ull a0x, a0y, b0x, b0y, a1x, a1y, b1x, b1y;
        if (q < NC) {
            a0x = cw[q][0]; a0y = cw[q][1];
            b0x = cw[q][2]; b0y = cw[q][3];
            a1x = cw[q][4]; a1y = cw[q][5];
            b1x = cw[q][6]; b1y = cw[q][7];
        } else {
            const float* r0 = wpl + (2*q  )*WR;
            const float* r1 = wpl + (2*q+1)*WR;
            ulonglong2 wA0 = *reinterpret_cast<const ulonglong2*>(r0);
            ulonglong2 wB0 = *reinterpret_cast<const ulonglong2*>(r0 + 208);
            ulonglong2 wA1 = *reinterpret_cast<const ulonglong2*>(r1);
            ulonglong2 wB1 = *reinterpret_cast<const ulonglong2*>(r1 + 208);
            a0x = wA0.x; a0y = wA0.y; b0x = wB0.x; b0y = wB0.y;
            a1x = wA1.x; a1y = wA1.y; b1x = wB1.x; b1y = wB1.y;
        }
        #pragma unroll
        for (int b = 0; b < 4; ++b) {
            ulonglong2 hv = *reinterpret_cast<const ulonglong2*>(hb + b*HRS + 4*q);
            acc[b][0] = ffma2(a0x, hv.x, acc[b][0]);
            acc[b][1] = ffma2(a0y, hv.x, acc[b][1]);
            acc[b][2] = ffma2(b0x, hv.x, acc[b][2]);
            acc[b][3] = ffma2(b0y, hv.x, acc[b][3]);
            acc[b][0] = ffma2(a1x, hv.y, acc[b][0]);
            acc[b][1] = ffma2(a1y, hv.y, acc[b][1]);
            acc[b][2] = ffma2(b1x, hv.y, acc[b][2]);
            acc[b][3] = ffma2(b1y, hv.y, acc[b][3]);
        }
    }
}

__device__ __forceinline__ void zacc(ull acc[4][4]) {
    #pragma unroll
    for (int b = 0; b < 4; ++b) {
        #pragma unroll
        for (int c = 0; c < 4; ++c) acc[b][c] = 0ull;
    }
}

__device__ __forceinline__ void loadquad(ull dst[8], const float* __restrict__ wq)
{
    const float* r0 = wq;
    const float* r1 = wq + WR;
    ulonglong2 wA0 = *reinterpret_cast<const ulonglong2*>(r0);
    ulonglong2 wB0 = *reinterpret_cast<const ulonglong2*>(r0 + 208);
    ulonglong2 wA1 = *reinterpret_cast<const ulonglong2*>(r1);
    ulonglong2 wB1 = *reinterpret_cast<const ulonglong2*>(r1 + 208);
    dst[0] = wA0.x; dst[1] = wA0.y; dst[2] = wB0.x; dst[3] = wB0.y;
    dst[4] = wA1.x; dst[5] = wA1.y; dst[6] = wB1.x; dst[7] = wB1.y;
}

// fused gate tail: fold parities, bias (+x*wx), cellup, store plain h.
__device__ __forceinline__ void gtail(ull acc[4][4], float cst[4],
                                      const float* __restrict__ bp,
                                      const float* __restrict__ wxp,
                                      const float* __restrict__ xv, bool withx,
                                      float* __restrict__ hdst, int uglob,
                                      bool act)
{
    if (!act) return;
    float4 bb = *reinterpret_cast<const float4*>(bp);
    float4 wx = withx ? *reinterpret_cast<const float4*>(wxp)
                      : make_float4(0.f, 0.f, 0.f, 0.f);
    #pragma unroll
    for (int b = 0; b < 4; ++b) {
        float gi = foldadd(acc[b][0]) + bb.x;
        float gf = foldadd(acc[b][1]) + bb.y;
        float gg = foldadd(acc[b][2]) + bb.z;
        float go = foldadd(acc[b][3]) + bb.w;
        if (withx) {
            gi = fmaf(xv[b], wx.x, gi);
            gf = fmaf(xv[b], wx.y, gf);
            gg = fmaf(xv[b], wx.z, gg);
            go = fmaf(xv[b], wx.w, go);
        }
        float hn = cellup(gi, gf, gg, go, cst[b]);
        hdst[b*HRS + uglob] = hn;
    }
}

// h2 . Wl reduce for one batch; result valid in ALL lanes (xor reduce).
__device__ __forceinline__ float outred(const float* __restrict__ h2row,
                                        const float* __restrict__ wl, int lane)
{
    float p = h2row[lane] * wl[lane];
    if (lane + 32 < H) p += h2row[lane + 32] * wl[lane + 32];
    #pragma unroll
    for (int o = 16; o > 0; o >>= 1)
        p += __shfl_xor_sync(0xffffffffu, p, o);
    return p;
}

__global__ void __launch_bounds__(NT, 1)
lstm_seq_kernel(const float* __restrict__ input,
                const float* __restrict__ Wih1, const float* __restrict__ Whh1,
                const float* __restrict__ bih1, const float* __restrict__ bhh1,
                const float* __restrict__ Wih2, const float* __restrict__ Whh2,
                const float* __restrict__ bih2, const float* __restrict__ bhh2,
                const float* __restrict__ Wl,   const float* __restrict__ bl,
                float* __restrict__ out)
{
    extern __shared__ __align__(16) float sm[];
    const int tid = threadIdx.x;
    const int cb0 = blockIdx.x * 8;

    // ---------- one-time prep ----------
    // weight kp-row layout: [A: u=0..51, 4 floats (c0e,c0o,c1e,c1o)]
    //                       [B: u=0..51, 4 floats (c2e,c2o,c3e,c3o)]
    // col j = 4u + c  <->  orig row = c*H + u (PyTorch gate order i,f,g,o)
    for (int idx = tid; idx < SZ_W1; idx += NT) {
        int kp = idx / WR, r = idx % WR;
        int part = (r >= 208) ? 1 : 0, rr = r - part*208;
        int u = rr >> 2, q = rr & 3;
        int c = part*2 + (q >> 1), par = q & 1;
        int k = 2*kp + par;
        sm[OFF_W1 + idx] = (u < H && k < H) ? Whh1[(c*H + u)*H + k] : 0.0f;
    }
    for (int idx = tid; idx < SZ_W2; idx += NT) {
        int kp = idx / WR, r = idx % WR;
        int part = (r >= 208) ? 1 : 0, rr = r - part*208;
        int u = rr >> 2, q = rr & 3;
        int c = part*2 + (q >> 1), par = q & 1;
        int k = 2*kp + par;          // 0..103: [h1 52 | h2 52]
        float v = 0.0f;
        if (u < H) {
            int row = (c*H + u)*H;
            if (k < H)                   v = Wih2[row + k];
            else if (k >= 52 && k < 103) v = Whh2[row + (k - 52)];
        }
        sm[OFF_W2 + idx] = v;
    }
    for (int j = tid; j < 256; j += NT) {
        int u = j >> 2, c = j & 3;
        float wx = 0.f, v1 = 0.f, v2 = 0.f;
        if (u < H && j < 208) {
            int row = c*H + u;
            wx = Wih1[row];
            v1 = bih1[row] + bhh1[row];
            v2 = bih2[row] + bhh2[row];
        }
        sm[OFF_WX + j] = wx;
        sm[OFF_B1 + j] = v1;
        sm[OFF_B2 + j] = v2;
    }
    // single writer per WL slot: 0..50 = Wl, 51..62 = 0, 63 = bl[0]
    if (tid < 64)
        sm[OFF_WL + tid] = (tid < H) ? Wl[tid]
                          : (tid == 63 ? bl[0] : 0.0f);
    for (int idx = tid; idx < 8*TSEQ; idx += NT) {
        int b = idx >> 9, tt = idx & 511;
        sm[OFF_GRP + (b >> 2)*GRPSZ + GIN + (b & 3)*INROW + tt]
            = input[cb0*TSEQ + idx];
    }
    for (int idx = tid; idx < 2*(GRPSZ - GH1); idx += NT) {
        int g = idx / (GRPSZ - GH1), r = idx % (GRPSZ - GH1);
        sm[OFF_GRP + g*GRPSZ + GH1 + r] = 0.0f;
    }
    __syncthreads();

    // ---------- roles ----------
    const int wid  = tid >> 5, lane = tid & 31;
    const int g    = wid >> 2;                    // group 0/1
    const int r4   = wid & 3;
    const int role = g ? (3 - r4) : r4;           // SMSP gets 1 heavy + 1 light
    const bool ismv2 = (role < 2);
    const int uh   = ismv2 ? role : (role - 2);   // unit-half
    const int uglob = uh*26 + lane;               // unit (lanes >=26 inactive)
    const bool act = (lane < 26);
    const int barid = 1 + g;

    float* SG = sm + OFF_GRP + g*GRPSZ;
    float* h1b0 = SG + GH1;
    float* h1b1 = SG + GH1 + 4*HRS;
    float* h2b0 = SG + GH2;
    float* h2b1 = SG + GH2 + 4*HRS;
    const float* wl = sm + OFF_WL;
    const float blv = sm[OFF_WL + 63];

    const float* w2p = sm + OFF_W2 + uglob*4;
    const float* w1p = sm + OFF_W1 + uglob*4;
    const float* b2p = sm + OFF_B2 + 4*uglob;
    const float* b1p = sm + OFF_B1 + 4*uglob;
    const float* wxp = sm + OFF_WX + 4*uglob;
    const int bgl = cb0 + g*4;

    // ---------- register-cached weight quads (loaded once) ----------
    ull cw[NC2][8];
    if (ismv2) {
        #pragma unroll
        for (int q = 0; q < NC2; ++q) loadquad(cw[q], w2p + 2*q*WR);
    } else {
        #pragma unroll
        for (int q = 0; q < NC1; ++q) loadquad(cw[q], w1p + 2*q*WR);
    }

    float cst[4] = {0.f, 0.f, 0.f, 0.f};    // c2 (mv2 warps) / c1 (mv1 warps)

    #define GBAR() asm volatile("bar.sync %0, %1;" :: "r"(barid), "r"(128) : "memory")

    // ---------- prologue: mv1(0) + g1(0) ----------
    if (!ismv2) {
        ull acc[4][4]; zacc(acc);
        mv13c<NC1, 13>(cw, w1p, h1b1, acc);     // h1(-1) = 0
        float xv[4];
        #pragma unroll
        for (int b = 0; b < 4; ++b) xv[b] = SG[GIN + b*INROW];
        gtail(acc, cst, b1p, wxp, xv, true, h1b0, uglob, act);
    }
    GBAR();

    for (int t = 0; t < TTOT; ++t) {
        float* h1w = (((t + 1) & 1) ? h1b1 : h1b0);
        const float* h1r = ((t & 1) ? h1b1 : h1b0);
        float* h2w = ((t & 1) ? h2b1 : h2b0);
        const float* h2r = (((t + 1) & 1) ? h2b1 : h2b0);   // h2(t-1)

        if (t < TSEQ - 1) {
            // ===== main region: ONE fat phase =====
            if (ismv2) {
                ull acc[4][4]; zacc(acc);
                mv13c<NC2, 13>(cw, w2p, h1r, acc);     // Wih2 @ h1(t)
                mv13c<0, 13>(cw, w2p + 26*WR, h2r, acc);   // Whh2 @ h2(t-1)
                gtail(acc, cst, b2p, 0, 0, false, h2w, uglob, act);
            } else {
                if (t > 0) {                          // out(t-1), 2 batches/warp
                    int bb = (role - 2)*2;
                    float p0 = outred(h2r + bb*HRS, wl, lane);
                    float p1 = outred(h2r + (bb + 1)*HRS, wl, lane);
                    if (lane == 0) {
                        out[(bgl + bb    )*TTOT + (t - 1)] = p0 + blv;
                        out[(bgl + bb + 1)*TTOT + (t - 1)] = p1 + blv;
                    }
                }
                ull acc[4][4]; zacc(acc);
                mv13c<NC1, 13>(cw, w1p, h1r, acc);     // Whh1 @ h1(t)
                float xv[4];
                #pragma unroll
                for (int b = 0; b < 4; ++b)
                    xv[b] = SG[GIN + b*INROW + (t + 1)];
                gtail(acc, cst, b1p, wxp, xv, true, h1w, uglob, act);
            }
            GBAR();
        } else {
            // ===== future-style step (out(t) feeds x(t+1)) =====
            // sub-A: mv2(t)+g2(t);  boundary-gap out(TSEQ-2)
            if (ismv2) {
                ull acc[4][4]; zacc(acc);
                mv13c<NC2, 13>(cw, w2p, h1r, acc);
                mv13c<0, 13>(cw, w2p + 26*WR, h2r, acc);
                gtail(acc, cst, b2p, 0, 0, false, h2w, uglob, act);
            } else if (t == TSEQ - 1) {
                int bb = (role - 2)*2;
                float p0 = outred(h2r + bb*HRS, wl, lane);
                float p1 = outred(h2r + (bb + 1)*HRS, wl, lane);
                if (lane == 0) {
                    out[(bgl + bb    )*TTOT + (t - 1)] = p0 + blv;
                    out[(bgl + bb + 1)*TTOT + (t - 1)] = p1 + blv;
                }
            }
            GBAR();
            // sub-B: out(t) (all lanes get value), then mv1(t+1)+g1(t+1)
            if (!ismv2) {
                float xv[4];
                #pragma unroll
                for (int b = 0; b < 4; ++b)
                    xv[b] = outred(h2w + b*HRS, wl, lane) + blv;
                if (role == 2 && lane == 0) {
                    #pragma unroll
                    for (int b = 0; b < 4; ++b)
                        out[(bgl + b)*TTOT + t] = xv[b];
                }
                if (t + 1 < TTOT) {
                    ull acc[4][4]; zacc(acc);
                    mv13c<NC1, 13>(cw, w1p, h1r, acc);
                    gtail(acc, cst, b1p, wxp, xv, true, h1w, uglob, act);
                }
            }
            GBAR();
        }
    }
    #undef GBAR
}

extern "C" void kernel_launch(void* const* d_in, const int* in_sizes, int n_in,
                              void* d_out, int out_size)
{
    (void)n_in; (void)out_size;
    cudaFuncSetAttribute(lstm_seq_kernel,
                         cudaFuncAttributeMaxDynamicSharedMemorySize, SMEM_BYTES);
    int nblocks = in_sizes[0] / (TSEQ * 8);   // B / 8 = 128
    lstm_seq_kernel<<<nblocks, NT, SMEM_BYTES>>>(
        (const float*)d_in[0],  (const float*)d_in[1], (const float*)d_in[2],
        (const float*)d_in[3],  (const float*)d_in[4], (const float*)d_in[5],
        (const float*)d_in[6],  (const float*)d_in[7], (const float*)d_in[8],
        (const float*)d_in[9],  (const float*)d_in[10],
        (float*)d_out);
}